// round 6
// baseline (speedup 1.0000x reference)
#include <cuda_runtime.h>
#include <stdint.h>
#include <math.h>

#define BATCH  4
#define NHEADS 16
#define HEAD   64
#define SEQ    2048
#define EMBED  1024
#define QKVN   3072
#define NTOK   (BATCH * SEQ)   // 8192

// ---------------- scratch (device globals: allocation-free) ----------------
__device__ float g_q[BATCH * NHEADS * SEQ * HEAD];   // [B,H,S,D], tf32-rounded, Q pre-scaled
__device__ float g_k[BATCH * NHEADS * SEQ * HEAD];
__device__ float g_v[BATCH * NHEADS * SEQ * HEAD];
__device__ float g_attn[BATCH * SEQ * EMBED];        // [B,S,H*D], tf32-rounded
__device__ float g_xr[NTOK * EMBED];                 // X, tf32-rounded
__device__ float g_wqkv[QKVN * EMBED];               // packed [n][k], tf32-rounded
__device__ float g_wo[EMBED * EMBED];                // Wo [e][f], tf32-rounded

// ---------------- helpers ----------------
__device__ __forceinline__ float rnd32(float f) {
    uint32_t r;
    asm("cvt.rna.tf32.f32 %0, %1;" : "=r"(r) : "f"(f));
    return __uint_as_float(r);
}

__device__ __forceinline__ void mma8(float* c,
                                     uint32_t a0, uint32_t a1, uint32_t a2, uint32_t a3,
                                     uint32_t b0, uint32_t b1) {
    asm volatile(
        "mma.sync.aligned.m16n8k8.row.col.f32.tf32.tf32.f32 "
        "{%0,%1,%2,%3}, {%4,%5,%6,%7}, {%8,%9}, {%0,%1,%2,%3};"
        : "+f"(c[0]), "+f"(c[1]), "+f"(c[2]), "+f"(c[3])
        : "r"(a0), "r"(a1), "r"(a2), "r"(a3), "r"(b0), "r"(b1));
}

__device__ __forceinline__ void ldsm4(uint32_t* r, const void* p) {
    uint32_t a = (uint32_t)__cvta_generic_to_shared(p);
    asm volatile("ldmatrix.sync.aligned.m8n8.x4.shared.b16 {%0,%1,%2,%3}, [%4];"
                 : "=r"(r[0]), "=r"(r[1]), "=r"(r[2]), "=r"(r[3]) : "r"(a));
}

__device__ __forceinline__ void cp16(void* smem, const void* gmem) {
    uint32_t sa = (uint32_t)__cvta_generic_to_shared(smem);
    asm volatile("cp.async.cg.shared.global [%0], [%1], 16;" :: "r"(sa), "l"(gmem));
}
#define CP_COMMIT() asm volatile("cp.async.commit_group;")
#define CP_WAIT1()  asm volatile("cp.async.wait_group 1;")

// smem sizes (bytes)
#define GEMM_SMEM ((3 * 256 * 20 + 3 * 128 * 20) * 4)            // 92160
#define ATTN_SMEM ((3 * 32 * 68 + 3 * 32 * 72 + 128 * 36) * 4)   // 72192

// ============================================================================
// Prep kernels
// ============================================================================
__global__ __launch_bounds__(256) void round_x_kernel(const float* __restrict__ x) {
    int i = (blockIdx.x * 256 + threadIdx.x) * 4;
    float4 v = *(const float4*)(x + i);
    v.x = rnd32(v.x); v.y = rnd32(v.y); v.z = rnd32(v.z); v.w = rnd32(v.w);
    *(float4*)(g_xr + i) = v;
}

// g_wqkv[n][k]: n -> (mat, head, d)
__global__ __launch_bounds__(256) void pack_w_kernel(
    const float* __restrict__ Wq, const float* __restrict__ Wk, const float* __restrict__ Wv) {
    int i = blockIdx.x * 256 + threadIdx.x;      // over QKVN*EMBED
    int n = i >> 10;
    int k = i & 1023;
    int mat = n >> 10;
    int hn  = n & 1023;
    int h = hn >> 6, d = hn & 63;
    const float* w = (mat == 0) ? Wq : ((mat == 1) ? Wk : Wv);
    g_wqkv[i] = rnd32(w[((size_t)h * EMBED + k) * HEAD + d]);
}

__global__ __launch_bounds__(256) void round_wo_kernel(const float* __restrict__ Wo) {
    int i = (blockIdx.x * 256 + threadIdx.x) * 4;
    float4 v = *(const float4*)(Wo + i);
    v.x = rnd32(v.x); v.y = rnd32(v.y); v.z = rnd32(v.z); v.w = rnd32(v.w);
    *(float4*)(g_wo + i) = v;
}

// ============================================================================
// GEMM body: C[256x128] = A[256xK] * B^T (B stored [n][k], k-contiguous).
// 8 warps = 4(M:64) x 2(N:64).  3-stage cp.async, ldmatrix fragment loads.
// ============================================================================
struct GemmAcc { float c[4][8][4]; };

__device__ __forceinline__ void gemm256_body(
    GemmAcc& acc,
    const float* __restrict__ aBase,   // A origin (row m0, col 0), row stride lda
    const float* __restrict__ bBase,   // B origin (row n0, col 0), row stride ldb
    int lda, int ldb, int NK)
{
    extern __shared__ float smem[];
    float (*As)[256][20] = (float(*)[256][20])smem;
    float (*Bs)[128][20] = (float(*)[128][20])(smem + 3 * 256 * 20);

    const int tid  = threadIdx.x;
    const int lane = tid & 31;
    const int warp = tid >> 5;
    const int wm   = warp & 3;         // M: 4 warps of 64 rows
    const int wn   = warp >> 2;        // N: 2 warps of 64 cols
    const int lmat = lane >> 3;        // ldmatrix sub-matrix id
    const int lrow = lane & 7;

    // staging: A 4 chunks/thread, B 2 chunks/thread (16B each)
    int ar[4], ac[4], br[2], bc[2];
    const float* agp[4];
    const float* bgp[2];
    #pragma unroll
    for (int j = 0; j < 4; j++) {
        int chunk = tid + j * 256;
        ar[j] = chunk >> 2; ac[j] = (chunk & 3) * 4;
        agp[j] = aBase + (size_t)ar[j] * lda + ac[j];
    }
    #pragma unroll
    for (int j = 0; j < 2; j++) {
        int chunk = tid + j * 256;
        br[j] = chunk >> 2; bc[j] = (chunk & 3) * 4;
        bgp[j] = bBase + (size_t)br[j] * ldb + bc[j];
    }

    // prologue: stages 0,1
    #pragma unroll
    for (int st = 0; st < 2; st++) {
        const int kc = st * 16;
        #pragma unroll
        for (int j = 0; j < 4; j++) cp16(&As[st][ar[j]][ac[j]], agp[j] + kc);
        #pragma unroll
        for (int j = 0; j < 2; j++) cp16(&Bs[st][br[j]][bc[j]], bgp[j] + kc);
        CP_COMMIT();
    }

    const int aRow0 = wm * 64 + (lmat & 1) * 8 + lrow;   // + mf*16
    const int bRow0 = wn * 64 + (lmat & 1) * 8 + lrow;   // + np*16
    const int kOff  = (lmat >> 1) * 4;                   // + kb

    int sc = 0;
    for (int it = 0; it < NK; it++) {
        CP_WAIT1();
        __syncthreads();

        if (it + 2 < NK) {
            int sp = sc + 2; if (sp >= 3) sp -= 3;
            const int kc = (it + 2) * 16;
            #pragma unroll
            for (int j = 0; j < 4; j++) cp16(&As[sp][ar[j]][ac[j]], agp[j] + kc);
            #pragma unroll
            for (int j = 0; j < 2; j++) cp16(&Bs[sp][br[j]][bc[j]], bgp[j] + kc);
            CP_COMMIT();
        }

        #pragma unroll
        for (int ks = 0; ks < 2; ks++) {
            const int kb = ks * 8 + kOff;
            uint32_t a[4][4], b[4][4];
            #pragma unroll
            for (int mf = 0; mf < 4; mf++)
                ldsm4(a[mf], &As[sc][aRow0 + mf * 16][kb]);
            #pragma unroll
            for (int np = 0; np < 4; np++)
                ldsm4(b[np], &Bs[sc][bRow0 + np * 16][kb]);
            // b[np][0]=b0(ni=2np) b[np][1]=b0(2np+1) b[np][2]=b1(2np) b[np][3]=b1(2np+1)
            #pragma unroll
            for (int mf = 0; mf < 4; mf++)
                #pragma unroll
                for (int np = 0; np < 4; np++) {
                    mma8(acc.c[mf][2 * np    ], a[mf][0], a[mf][1], a[mf][2], a[mf][3],
                         b[np][0], b[np][2]);
                    mma8(acc.c[mf][2 * np + 1], a[mf][0], a[mf][1], a[mf][2], a[mf][3],
                         b[np][1], b[np][3]);
                }
        }

        if (++sc == 3) sc = 0;
    }
}

// ============================================================================
// Kernel 1: QKV GEMM -> scatter to g_q/g_k/g_v [B,H,S,D].
// ============================================================================
__global__ __launch_bounds__(256, 1) void qkv_kernel()
{
    const int n0 = blockIdx.x * 128;
    const int m0 = blockIdx.y * 256;

    GemmAcc acc;
    #pragma unroll
    for (int mf = 0; mf < 4; mf++)
        #pragma unroll
        for (int ni = 0; ni < 8; ni++)
            #pragma unroll
            for (int e = 0; e < 4; e++) acc.c[mf][ni][e] = 0.0f;

    gemm256_body(acc, g_xr + (size_t)m0 * EMBED, g_wqkv + (size_t)n0 * EMBED,
                 EMBED, EMBED, EMBED / 16);

    const int lane = threadIdx.x & 31;
    const int warp = threadIdx.x >> 5;
    const int g    = lane >> 2;
    const int t4   = lane & 3;
    const int wm   = warp & 3;
    const int wn   = warp >> 2;

    const int mat = n0 >> 10;
    const int b   = m0 >> 11;
    const int s0l = m0 & 2047;
    const int h   = ((n0 & 1023) + wn * 64) >> 6;
    float* dstm = (mat == 0) ? g_q : ((mat == 1) ? g_k : g_v);
    float* dst  = dstm + ((size_t)(b * NHEADS + h) * SEQ) * HEAD;
    const float scale = (mat == 0) ? 0.125f : 1.0f;

    #pragma unroll
    for (int mf = 0; mf < 4; mf++) {
        int s0r = s0l + wm * 64 + mf * 16 + g;
        #pragma unroll
        for (int ni = 0; ni < 8; ni++) {
            int d = ni * 8 + t4 * 2;
            dst[(size_t)(s0r    ) * HEAD + d    ] = rnd32(acc.c[mf][ni][0] * scale);
            dst[(size_t)(s0r    ) * HEAD + d + 1] = rnd32(acc.c[mf][ni][1] * scale);
            dst[(size_t)(s0r + 8) * HEAD + d    ] = rnd32(acc.c[mf][ni][2] * scale);
            dst[(size_t)(s0r + 8) * HEAD + d + 1] = rnd32(acc.c[mf][ni][3] * scale);
        }
    }
}

// ============================================================================
// Kernel 2: causal flash attention (unchanged from R5).
// ============================================================================
__global__ __launch_bounds__(256, 1) void attn_kernel()
{
    extern __shared__ float smem[];
    float (*Ks)[32][68] = (float(*)[32][68])smem;
    float (*Vs)[32][72] = (float(*)[32][72])(smem + 3 * 32 * 68);
    float (*Ps)[36]     = (float(*)[36])(smem + 3 * 32 * 68 + 3 * 32 * 72);

    const int bh = blockIdx.y;
    const int b  = bh >> 4;
    const int h  = bh & 15;
    const int qt = blockIdx.x;
    const int q0 = qt * 128;

    const int tid  = threadIdx.x;
    const int lane = tid & 31;
    const int warp = tid >> 5;
    const int g    = lane >> 2;
    const int t4   = lane & 3;

    const float* qp = g_q + ((size_t)bh * SEQ + q0) * HEAD;
    const float* kp = g_k + (size_t)bh * SEQ * HEAD;
    const float* vp = g_v + (size_t)bh * SEQ * HEAD;

    int cr[2], cd[2];
    #pragma unroll
    for (int j = 0; j < 2; j++) {
        int chunk = tid + j * 256;
        cr[j] = chunk >> 4; cd[j] = (chunk & 15) * 4;
    }

    uint32_t qa[8][4];
    #pragma unroll
    for (int round = 0; round < 2; round++) {
        const int c0 = round * 32;
        #pragma unroll
        for (int i = tid; i < 128 * 32; i += 256) {
            int r = i >> 5, cc = i & 31;
            Ps[r][cc] = qp[(size_t)r * HEAD + c0 + cc];
        }
        __syncthreads();
        #pragma unroll
        for (int kf = 0; kf < 4; kf++) {
            int kfi = round * 4 + kf;
            int rr = warp * 16;
            qa[kfi][0] = __float_as_uint(Ps[rr + g    ][kf * 8 + t4]);
            qa[kfi][1] = __float_as_uint(Ps[rr + g + 8][kf * 8 + t4]);
            qa[kfi][2] = __float_as_uint(Ps[rr + g    ][kf * 8 + t4 + 4]);
            qa[kfi][3] = __float_as_uint(Ps[rr + g + 8][kf * 8 + t4 + 4]);
        }
        __syncthreads();
    }

    float o[8][4];
    #pragma unroll
    for (int dn = 0; dn < 8; dn++)
        #pragma unroll
        for (int e = 0; e < 4; e++) o[dn][e] = 0.0f;

    float m0 = -1e30f, m1 = -1e30f, l0 = 0.0f, l1 = 0.0f;

    const int nkt   = (qt + 1) * 4;
    const int row0b = q0 + warp * 16;
    const int qmaxw = row0b + 15;

    #pragma unroll
    for (int st = 0; st < 2; st++) {
        const size_t base = (size_t)st * 32 * HEAD;
        #pragma unroll
        for (int j = 0; j < 2; j++) {
            cp16(&Ks[st][cr[j]][cd[j]], kp + base + (size_t)cr[j] * HEAD + cd[j]);
            cp16(&Vs[st][cr[j]][cd[j]], vp + base + (size_t)cr[j] * HEAD + cd[j]);
        }
        CP_COMMIT();
    }

    int sc = 0;
    for (int kt = 0; kt < nkt; kt++) {
        const int k0 = kt * 32;

        CP_WAIT1();
        __syncthreads();

        if (kt + 2 < nkt) {
            int sp = sc + 2; if (sp >= 3) sp -= 3;
            const size_t base = (size_t)(k0 + 64) * HEAD;
            #pragma unroll
            for (int j = 0; j < 2; j++) {
                cp16(&Ks[sp][cr[j]][cd[j]], kp + base + (size_t)cr[j] * HEAD + cd[j]);
                cp16(&Vs[sp][cr[j]][cd[j]], vp + base + (size_t)cr[j] * HEAD + cd[j]);
            }
            CP_COMMIT();
        }

        if (k0 <= qmaxw) {
            float s[4][4];
            #pragma unroll
            for (int nf = 0; nf < 4; nf++)
                #pragma unroll
                for (int e = 0; e < 4; e++) s[nf][e] = 0.0f;

            #pragma unroll
            for (int kf = 0; kf < 8; kf++) {
                #pragma unroll
                for (int nf = 0; nf < 4; nf++) {
                    uint32_t b0 = __float_as_uint(Ks[sc][nf * 8 + g][kf * 8 + t4]);
                    uint32_t b1 = __float_as_uint(Ks[sc][nf * 8 + g][kf * 8 + t4 + 4]);
                    mma8(s[nf], qa[kf][0], qa[kf][1], qa[kf][2], qa[kf][3], b0, b1);
                }
            }

            const int r0 = row0b + g;
            const int r1 = r0 + 8;
            #pragma unroll
            for (int nf = 0; nf < 4; nf++) {
                int col0 = k0 + nf * 8 + t4 * 2;
                if (col0     > r0) s[nf][0] = -1e30f;
                if (col0 + 1 > r0) s[nf][1] = -1e30f;
                if (col0     > r1) s[nf][2] = -1e30f;
                if (col0 + 1 > r1) s[nf][3] = -1e30f;
            }

            float rm0 = -1e30f, rm1 = -1e30f;
            #pragma unroll
            for (int nf = 0; nf < 4; nf++) {
                rm0 = fmaxf(rm0, fmaxf(s[nf][0], s[nf][1]));
                rm1 = fmaxf(rm1, fmaxf(s[nf][2], s[nf][3]));
            }
            rm0 = fmaxf(rm0, __shfl_xor_sync(0xffffffffu, rm0, 1));
            rm0 = fmaxf(rm0, __shfl_xor_sync(0xffffffffu, rm0, 2));
            rm1 = fmaxf(rm1, __shfl_xor_sync(0xffffffffu, rm1, 1));
            rm1 = fmaxf(rm1, __shfl_xor_sync(0xffffffffu, rm1, 2));

            float nm0 = fmaxf(m0, rm0), nm1 = fmaxf(m1, rm1);
            float sc0 = __expf(m0 - nm0), sc1 = __expf(m1 - nm1);

            float sum0 = 0.0f, sum1 = 0.0f;
            const int rr = warp * 16;
            #pragma unroll
            for (int nf = 0; nf < 4; nf++) {
                float p0 = rnd32(__expf(s[nf][0] - nm0));
                float p1 = rnd32(__expf(s[nf][1] - nm0));
                float p2 = rnd32(__expf(s[nf][2] - nm1));
                float p3 = rnd32(__expf(s[nf][3] - nm1));
                Ps[rr + g    ][nf * 8 + t4 * 2    ] = p0;
                Ps[rr + g    ][nf * 8 + t4 * 2 + 1] = p1;
                Ps[rr + g + 8][nf * 8 + t4 * 2    ] = p2;
                Ps[rr + g + 8][nf * 8 + t4 * 2 + 1] = p3;
                sum0 += p0 + p1;
                sum1 += p2 + p3;
            }
            sum0 += __shfl_xor_sync(0xffffffffu, sum0, 1);
            sum0 += __shfl_xor_sync(0xffffffffu, sum0, 2);
            sum1 += __shfl_xor_sync(0xffffffffu, sum1, 1);
            sum1 += __shfl_xor_sync(0xffffffffu, sum1, 2);

            l0 = l0 * sc0 + sum0;  m0 = nm0;
            l1 = l1 * sc1 + sum1;  m1 = nm1;

            #pragma unroll
            for (int dn = 0; dn < 8; dn++) {
                o[dn][0] *= sc0; o[dn][1] *= sc0;
                o[dn][2] *= sc1; o[dn][3] *= sc1;
            }
            __syncwarp();

            #pragma unroll
            for (int kf = 0; kf < 4; kf++) {
                uint32_t pa0 = __float_as_uint(Ps[rr + g    ][kf * 8 + t4]);
                uint32_t pa1 = __float_as_uint(Ps[rr + g + 8][kf * 8 + t4]);
                uint32_t pa2 = __float_as_uint(Ps[rr + g    ][kf * 8 + t4 + 4]);
                uint32_t pa3 = __float_as_uint(Ps[rr + g + 8][kf * 8 + t4 + 4]);
                #pragma unroll
                for (int dn = 0; dn < 8; dn++) {
                    uint32_t b0 = __float_as_uint(Vs[sc][kf * 8 + t4    ][dn * 8 + g]);
                    uint32_t b1 = __float_as_uint(Vs[sc][kf * 8 + t4 + 4][dn * 8 + g]);
                    mma8(o[dn], pa0, pa1, pa2, pa3, b0, b1);
                }
            }
            __syncwarp();
        }

        if (++sc == 3) sc = 0;
    }

    const float inv0 = 1.0f / l0;
    const float inv1 = 1.0f / l1;
    const int r0 = q0 + warp * 16 + g;
    float* ob = g_attn + (size_t)b * SEQ * EMBED + (size_t)h * HEAD;
    #pragma unroll
    for (int dn = 0; dn < 8; dn++) {
        int d = dn * 8 + t4 * 2;
        ob[(size_t)(r0    ) * EMBED + d    ] = rnd32(o[dn][0] * inv0);
        ob[(size_t)(r0    ) * EMBED + d + 1] = rnd32(o[dn][1] * inv0);
        ob[(size_t)(r0 + 8) * EMBED + d    ] = rnd32(o[dn][2] * inv1);
        ob[(size_t)(r0 + 8) * EMBED + d + 1] = rnd32(o[dn][3] * inv1);
    }
}

// ============================================================================
// Kernel 3: output projection.  g_attn[8192,1024] @ g_wo^T + bo.
// ============================================================================
__global__ __launch_bounds__(256, 1) void proj_kernel(
    const float* __restrict__ bo,
    float* __restrict__ out)
{
    const int e0 = blockIdx.x * 128;
    const int m0 = blockIdx.y * 256;

    GemmAcc acc;
    #pragma unroll
    for (int mf = 0; mf < 4; mf++)
        #pragma unroll
        for (int ni = 0; ni < 8; ni++)
            #pragma unroll
            for (int e = 0; e < 4; e++) acc.c[mf][ni][e] = 0.0f;

    gemm256_body(acc, g_attn + (size_t)m0 * EMBED, g_wo + (size_t)e0 * EMBED,
                 EMBED, EMBED, EMBED / 16);

    const int lane = threadIdx.x & 31;
    const int warp = threadIdx.x >> 5;
    const int g    = lane >> 2;
    const int t4   = lane & 3;
    const int wm   = warp & 3;
    const int wn   = warp >> 2;

    #pragma unroll
    for (int mf = 0; mf < 4; mf++) {
        int r0 = m0 + wm * 64 + mf * 16 + g;
        #pragma unroll
        for (int ni = 0; ni < 8; ni++) {
            int e = e0 + wn * 64 + ni * 8 + t4 * 2;
            out[(size_t)(r0    ) * EMBED + e    ] = acc.c[mf][ni][0] + bo[e];
            out[(size_t)(r0    ) * EMBED + e + 1] = acc.c[mf][ni][1] + bo[e + 1];
            out[(size_t)(r0 + 8) * EMBED + e    ] = acc.c[mf][ni][2] + bo[e];
            out[(size_t)(r0 + 8) * EMBED + e + 1] = acc.c[mf][ni][3] + bo[e + 1];
        }
    }
}

// ============================================================================
extern "C" void kernel_launch(void* const* d_in, const int* in_sizes, int n_in,
                              void* d_out, int out_size)
{
    const float* x  = (const float*)d_in[0];
    const float* Wq = (const float*)d_in[1];
    const float* Wk = (const float*)d_in[2];
    const float* Wv = (const float*)d_in[3];
    const float* Wo = (const float*)d_in[4];
    const float* bo = (const float*)d_in[5];
    float* out = (float*)d_out;

    (void)in_sizes; (void)n_in; (void)out_size;

    cudaFuncSetAttribute(qkv_kernel,  cudaFuncAttributeMaxDynamicSharedMemorySize, GEMM_SMEM);
    cudaFuncSetAttribute(attn_kernel, cudaFuncAttributeMaxDynamicSharedMemorySize, ATTN_SMEM);
    cudaFuncSetAttribute(proj_kernel, cudaFuncAttributeMaxDynamicSharedMemorySize, GEMM_SMEM);

    round_x_kernel<<<NTOK * EMBED / 1024, 256>>>(x);
    pack_w_kernel<<<QKVN * EMBED / 256, 256>>>(Wq, Wk, Wv);
    round_wo_kernel<<<EMBED * EMBED / 1024, 256>>>(Wo);

    qkv_kernel<<<dim3(QKVN / 128, NTOK / 256), 256, GEMM_SMEM>>>();
    attn_kernel<<<dim3(SEQ / 128, BATCH * NHEADS), 256, ATTN_SMEM>>>();
    proj_kernel<<<dim3(EMBED / 128, NTOK / 256), 256, GEMM_SMEM>>>(bo, out);
}

// round 7
// speedup vs baseline: 1.0694x; 1.0694x over previous
#include <cuda_runtime.h>
#include <stdint.h>
#include <math.h>

#define BATCH  4
#define NHEADS 16
#define HEAD   64
#define SEQ    2048
#define EMBED  1024
#define QKVN   3072
#define NTOK   (BATCH * SEQ)   // 8192

// ---------------- scratch (device globals: allocation-free) ----------------
__device__ float g_q[BATCH * NHEADS * SEQ * HEAD];   // [B,H,S,D], tf32-rounded, Q pre-scaled
__device__ float g_k[BATCH * NHEADS * SEQ * HEAD];
__device__ float g_v[BATCH * NHEADS * SEQ * HEAD];
__device__ float g_attn[BATCH * SEQ * EMBED];        // [B,S,H*D], tf32-rounded
__device__ float g_xr[NTOK * EMBED];                 // X, tf32-rounded
__device__ float g_wqkv[QKVN * EMBED];               // packed [n][k], tf32-rounded
__device__ float g_wo[EMBED * EMBED];                // Wo [e][f], tf32-rounded

// ---------------- helpers ----------------
__device__ __forceinline__ float rnd32(float f) {
    uint32_t r;
    asm("cvt.rna.tf32.f32 %0, %1;" : "=r"(r) : "f"(f));
    return __uint_as_float(r);
}

__device__ __forceinline__ void mma8(float* c,
                                     uint32_t a0, uint32_t a1, uint32_t a2, uint32_t a3,
                                     uint32_t b0, uint32_t b1) {
    asm volatile(
        "mma.sync.aligned.m16n8k8.row.col.f32.tf32.tf32.f32 "
        "{%0,%1,%2,%3}, {%4,%5,%6,%7}, {%8,%9}, {%0,%1,%2,%3};"
        : "+f"(c[0]), "+f"(c[1]), "+f"(c[2]), "+f"(c[3])
        : "r"(a0), "r"(a1), "r"(a2), "r"(a3), "r"(b0), "r"(b1));
}

__device__ __forceinline__ void ldsm4(uint32_t* r, const void* p) {
    uint32_t a = (uint32_t)__cvta_generic_to_shared(p);
    asm volatile("ldmatrix.sync.aligned.m8n8.x4.shared.b16 {%0,%1,%2,%3}, [%4];"
                 : "=r"(r[0]), "=r"(r[1]), "=r"(r[2]), "=r"(r[3]) : "r"(a));
}

__device__ __forceinline__ void cp16(void* smem, const void* gmem) {
    uint32_t sa = (uint32_t)__cvta_generic_to_shared(smem);
    asm volatile("cp.async.cg.shared.global [%0], [%1], 16;" :: "r"(sa), "l"(gmem));
}
#define CP_COMMIT() asm volatile("cp.async.commit_group;")
#define CP_WAIT1()  asm volatile("cp.async.wait_group 1;")

// smem sizes (bytes)
#define GEMM_SMEM ((3 * 128 * 20 + 3 * 128 * 20) * 4)            // 61440
#define ATTN_SMEM ((3 * 32 * 68 + 3 * 32 * 72 + 128 * 36) * 4)   // 72192

// ============================================================================
// Prep kernels
// ============================================================================
__global__ __launch_bounds__(256) void round_x_kernel(const float* __restrict__ x) {
    int i = (blockIdx.x * 256 + threadIdx.x) * 4;
    float4 v = *(const float4*)(x + i);
    v.x = rnd32(v.x); v.y = rnd32(v.y); v.z = rnd32(v.z); v.w = rnd32(v.w);
    *(float4*)(g_xr + i) = v;
}

// g_wqkv[n][k]: n -> (mat, head, d)
__global__ __launch_bounds__(256) void pack_w_kernel(
    const float* __restrict__ Wq, const float* __restrict__ Wk, const float* __restrict__ Wv) {
    int i = blockIdx.x * 256 + threadIdx.x;      // over QKVN*EMBED
    int n = i >> 10;
    int k = i & 1023;
    int mat = n >> 10;
    int hn  = n & 1023;
    int h = hn >> 6, d = hn & 63;
    const float* w = (mat == 0) ? Wq : ((mat == 1) ? Wk : Wv);
    g_wqkv[i] = rnd32(w[((size_t)h * EMBED + k) * HEAD + d]);
}

__global__ __launch_bounds__(256) void round_wo_kernel(const float* __restrict__ Wo) {
    int i = (blockIdx.x * 256 + threadIdx.x) * 4;
    float4 v = *(const float4*)(Wo + i);
    v.x = rnd32(v.x); v.y = rnd32(v.y); v.z = rnd32(v.z); v.w = rnd32(v.w);
    *(float4*)(g_wo + i) = v;
}

// ============================================================================
// GEMM body: C[128x128] = A[128xK] * B^T (B stored [n][k], k-contiguous).
// 4 warps = 2(M:64) x 2(N:64), 128 threads.  3-stage cp.async, ldmatrix.
// ============================================================================
struct GemmAcc { float c[4][8][4]; };

__device__ __forceinline__ void gemm128_body(
    GemmAcc& acc,
    const float* __restrict__ aBase,   // A origin (row m0, col 0), row stride lda
    const float* __restrict__ bBase,   // B origin (row n0, col 0), row stride ldb
    int lda, int ldb, int NK)
{
    extern __shared__ float smem[];
    float (*As)[128][20] = (float(*)[128][20])smem;
    float (*Bs)[128][20] = (float(*)[128][20])(smem + 3 * 128 * 20);

    const int tid  = threadIdx.x;      // 0..127
    const int lane = tid & 31;
    const int warp = tid >> 5;         // 0..3
    const int wm   = warp & 1;         // M: 2 warps of 64 rows
    const int wn   = warp >> 1;        // N: 2 warps of 64 cols
    const int lmat = lane >> 3;
    const int lrow = lane & 7;

    // staging: A 4 chunks/thread, B 4 chunks/thread (16B each)
    int ar[4], ac[4], br[4], bc[4];
    const float* agp[4];
    const float* bgp[4];
    #pragma unroll
    for (int j = 0; j < 4; j++) {
        int chunk = tid + j * 128;
        ar[j] = chunk >> 2; ac[j] = (chunk & 3) * 4;
        agp[j] = aBase + (size_t)ar[j] * lda + ac[j];
        br[j] = ar[j]; bc[j] = ac[j];
        bgp[j] = bBase + (size_t)br[j] * ldb + bc[j];
    }

    // prologue: stages 0,1
    #pragma unroll
    for (int st = 0; st < 2; st++) {
        const int kc = st * 16;
        #pragma unroll
        for (int j = 0; j < 4; j++) cp16(&As[st][ar[j]][ac[j]], agp[j] + kc);
        #pragma unroll
        for (int j = 0; j < 4; j++) cp16(&Bs[st][br[j]][bc[j]], bgp[j] + kc);
        CP_COMMIT();
    }

    const int aRow0 = wm * 64 + (lmat & 1) * 8 + lrow;   // + mf*16
    const int bRow0 = wn * 64 + (lmat & 1) * 8 + lrow;   // + np*16
    const int kOff  = (lmat >> 1) * 4;                   // + kb

    int sc = 0;
    for (int it = 0; it < NK; it++) {
        CP_WAIT1();
        __syncthreads();

        if (it + 2 < NK) {
            int sp = sc + 2; if (sp >= 3) sp -= 3;
            const int kc = (it + 2) * 16;
            #pragma unroll
            for (int j = 0; j < 4; j++) cp16(&As[sp][ar[j]][ac[j]], agp[j] + kc);
            #pragma unroll
            for (int j = 0; j < 4; j++) cp16(&Bs[sp][br[j]][bc[j]], bgp[j] + kc);
            CP_COMMIT();
        }

        #pragma unroll
        for (int ks = 0; ks < 2; ks++) {
            const int kb = ks * 8 + kOff;
            uint32_t a[4][4], b[4][4];
            #pragma unroll
            for (int mf = 0; mf < 4; mf++)
                ldsm4(a[mf], &As[sc][aRow0 + mf * 16][kb]);
            #pragma unroll
            for (int np = 0; np < 4; np++)
                ldsm4(b[np], &Bs[sc][bRow0 + np * 16][kb]);
            #pragma unroll
            for (int mf = 0; mf < 4; mf++)
                #pragma unroll
                for (int np = 0; np < 4; np++) {
                    mma8(acc.c[mf][2 * np    ], a[mf][0], a[mf][1], a[mf][2], a[mf][3],
                         b[np][0], b[np][2]);
                    mma8(acc.c[mf][2 * np + 1], a[mf][0], a[mf][1], a[mf][2], a[mf][3],
                         b[np][1], b[np][3]);
                }
        }

        if (++sc == 3) sc = 0;
    }
}

// ============================================================================
// Kernel 1: QKV GEMM -> scatter to g_q/g_k/g_v [B,H,S,D].
// ============================================================================
__global__ __launch_bounds__(128, 2) void qkv_kernel()
{
    const int n0 = blockIdx.x * 128;
    const int m0 = blockIdx.y * 128;

    GemmAcc acc;
    #pragma unroll
    for (int mf = 0; mf < 4; mf++)
        #pragma unroll
        for (int ni = 0; ni < 8; ni++)
            #pragma unroll
            for (int e = 0; e < 4; e++) acc.c[mf][ni][e] = 0.0f;

    gemm128_body(acc, g_xr + (size_t)m0 * EMBED, g_wqkv + (size_t)n0 * EMBED,
                 EMBED, EMBED, EMBED / 16);

    const int lane = threadIdx.x & 31;
    const int warp = threadIdx.x >> 5;
    const int g    = lane >> 2;
    const int t4   = lane & 3;
    const int wm   = warp & 1;
    const int wn   = warp >> 1;

    const int mat = n0 >> 10;
    const int b   = m0 >> 11;
    const int s0l = m0 & 2047;
    const int h   = ((n0 & 1023) + wn * 64) >> 6;
    float* dstm = (mat == 0) ? g_q : ((mat == 1) ? g_k : g_v);
    float* dst  = dstm + ((size_t)(b * NHEADS + h) * SEQ) * HEAD;
    const float scale = (mat == 0) ? 0.125f : 1.0f;

    #pragma unroll
    for (int mf = 0; mf < 4; mf++) {
        int s0r = s0l + wm * 64 + mf * 16 + g;
        #pragma unroll
        for (int ni = 0; ni < 8; ni++) {
            int d = ni * 8 + t4 * 2;
            dst[(size_t)(s0r    ) * HEAD + d    ] = rnd32(acc.c[mf][ni][0] * scale);
            dst[(size_t)(s0r    ) * HEAD + d + 1] = rnd32(acc.c[mf][ni][1] * scale);
            dst[(size_t)(s0r + 8) * HEAD + d    ] = rnd32(acc.c[mf][ni][2] * scale);
            dst[(size_t)(s0r + 8) * HEAD + d + 1] = rnd32(acc.c[mf][ni][3] * scale);
        }
    }
}

// ============================================================================
// Kernel 2: causal flash attention (R5 version, proven).
// BM=128 (8 warps x 16 rows), BN=32, D=64, 3-stage cp.async K/V ring.
// ============================================================================
__global__ __launch_bounds__(256, 1) void attn_kernel()
{
    extern __shared__ float smem[];
    float (*Ks)[32][68] = (float(*)[32][68])smem;
    float (*Vs)[32][72] = (float(*)[32][72])(smem + 3 * 32 * 68);
    float (*Ps)[36]     = (float(*)[36])(smem + 3 * 32 * 68 + 3 * 32 * 72);

    const int bh = blockIdx.y;
    const int b  = bh >> 4;
    const int h  = bh & 15;
    const int qt = blockIdx.x;
    const int q0 = qt * 128;

    const int tid  = threadIdx.x;
    const int lane = tid & 31;
    const int warp = tid >> 5;
    const int g    = lane >> 2;
    const int t4   = lane & 3;

    const float* qp = g_q + ((size_t)bh * SEQ + q0) * HEAD;
    const float* kp = g_k + (size_t)bh * SEQ * HEAD;
    const float* vp = g_v + (size_t)bh * SEQ * HEAD;

    int cr[2], cd[2];
    #pragma unroll
    for (int j = 0; j < 2; j++) {
        int chunk = tid + j * 256;
        cr[j] = chunk >> 4; cd[j] = (chunk & 15) * 4;
    }

    uint32_t qa[8][4];
    #pragma unroll
    for (int round = 0; round < 2; round++) {
        const int c0 = round * 32;
        #pragma unroll
        for (int i = tid; i < 128 * 32; i += 256) {
            int r = i >> 5, cc = i & 31;
            Ps[r][cc] = qp[(size_t)r * HEAD + c0 + cc];
        }
        __syncthreads();
        #pragma unroll
        for (int kf = 0; kf < 4; kf++) {
            int kfi = round * 4 + kf;
            int rr = warp * 16;
            qa[kfi][0] = __float_as_uint(Ps[rr + g    ][kf * 8 + t4]);
            qa[kfi][1] = __float_as_uint(Ps[rr + g + 8][kf * 8 + t4]);
            qa[kfi][2] = __float_as_uint(Ps[rr + g    ][kf * 8 + t4 + 4]);
            qa[kfi][3] = __float_as_uint(Ps[rr + g + 8][kf * 8 + t4 + 4]);
        }
        __syncthreads();
    }

    float o[8][4];
    #pragma unroll
    for (int dn = 0; dn < 8; dn++)
        #pragma unroll
        for (int e = 0; e < 4; e++) o[dn][e] = 0.0f;

    float m0 = -1e30f, m1 = -1e30f, l0 = 0.0f, l1 = 0.0f;

    const int nkt   = (qt + 1) * 4;
    const int row0b = q0 + warp * 16;
    const int qmaxw = row0b + 15;

    #pragma unroll
    for (int st = 0; st < 2; st++) {
        const size_t base = (size_t)st * 32 * HEAD;
        #pragma unroll
        for (int j = 0; j < 2; j++) {
            cp16(&Ks[st][cr[j]][cd[j]], kp + base + (size_t)cr[j] * HEAD + cd[j]);
            cp16(&Vs[st][cr[j]][cd[j]], vp + base + (size_t)cr[j] * HEAD + cd[j]);
        }
        CP_COMMIT();
    }

    int sc = 0;
    for (int kt = 0; kt < nkt; kt++) {
        const int k0 = kt * 32;

        CP_WAIT1();
        __syncthreads();

        if (kt + 2 < nkt) {
            int sp = sc + 2; if (sp >= 3) sp -= 3;
            const size_t base = (size_t)(k0 + 64) * HEAD;
            #pragma unroll
            for (int j = 0; j < 2; j++) {
                cp16(&Ks[sp][cr[j]][cd[j]], kp + base + (size_t)cr[j] * HEAD + cd[j]);
                cp16(&Vs[sp][cr[j]][cd[j]], vp + base + (size_t)cr[j] * HEAD + cd[j]);
            }
            CP_COMMIT();
        }

        if (k0 <= qmaxw) {
            float s[4][4];
            #pragma unroll
            for (int nf = 0; nf < 4; nf++)
                #pragma unroll
                for (int e = 0; e < 4; e++) s[nf][e] = 0.0f;

            #pragma unroll
            for (int kf = 0; kf < 8; kf++) {
                #pragma unroll
                for (int nf = 0; nf < 4; nf++) {
                    uint32_t b0 = __float_as_uint(Ks[sc][nf * 8 + g][kf * 8 + t4]);
                    uint32_t b1 = __float_as_uint(Ks[sc][nf * 8 + g][kf * 8 + t4 + 4]);
                    mma8(s[nf], qa[kf][0], qa[kf][1], qa[kf][2], qa[kf][3], b0, b1);
                }
            }

            const int r0 = row0b + g;
            const int r1 = r0 + 8;
            #pragma unroll
            for (int nf = 0; nf < 4; nf++) {
                int col0 = k0 + nf * 8 + t4 * 2;
                if (col0     > r0) s[nf][0] = -1e30f;
                if (col0 + 1 > r0) s[nf][1] = -1e30f;
                if (col0     > r1) s[nf][2] = -1e30f;
                if (col0 + 1 > r1) s[nf][3] = -1e30f;
            }

            float rm0 = -1e30f, rm1 = -1e30f;
            #pragma unroll
            for (int nf = 0; nf < 4; nf++) {
                rm0 = fmaxf(rm0, fmaxf(s[nf][0], s[nf][1]));
                rm1 = fmaxf(rm1, fmaxf(s[nf][2], s[nf][3]));
            }
            rm0 = fmaxf(rm0, __shfl_xor_sync(0xffffffffu, rm0, 1));
            rm0 = fmaxf(rm0, __shfl_xor_sync(0xffffffffu, rm0, 2));
            rm1 = fmaxf(rm1, __shfl_xor_sync(0xffffffffu, rm1, 1));
            rm1 = fmaxf(rm1, __shfl_xor_sync(0xffffffffu, rm1, 2));

            float nm0 = fmaxf(m0, rm0), nm1 = fmaxf(m1, rm1);
            float sc0 = __expf(m0 - nm0), sc1 = __expf(m1 - nm1);

            float sum0 = 0.0f, sum1 = 0.0f;
            const int rr = warp * 16;
            #pragma unroll
            for (int nf = 0; nf < 4; nf++) {
                float p0 = rnd32(__expf(s[nf][0] - nm0));
                float p1 = rnd32(__expf(s[nf][1] - nm0));
                float p2 = rnd32(__expf(s[nf][2] - nm1));
                float p3 = rnd32(__expf(s[nf][3] - nm1));
                Ps[rr + g    ][nf * 8 + t4 * 2    ] = p0;
                Ps[rr + g    ][nf * 8 + t4 * 2 + 1] = p1;
                Ps[rr + g + 8][nf * 8 + t4 * 2    ] = p2;
                Ps[rr + g + 8][nf * 8 + t4 * 2 + 1] = p3;
                sum0 += p0 + p1;
                sum1 += p2 + p3;
            }
            sum0 += __shfl_xor_sync(0xffffffffu, sum0, 1);
            sum0 += __shfl_xor_sync(0xffffffffu, sum0, 2);
            sum1 += __shfl_xor_sync(0xffffffffu, sum1, 1);
            sum1 += __shfl_xor_sync(0xffffffffu, sum1, 2);

            l0 = l0 * sc0 + sum0;  m0 = nm0;
            l1 = l1 * sc1 + sum1;  m1 = nm1;

            #pragma unroll
            for (int dn = 0; dn < 8; dn++) {
                o[dn][0] *= sc0; o[dn][1] *= sc0;
                o[dn][2] *= sc1; o[dn][3] *= sc1;
            }
            __syncwarp();

            #pragma unroll
            for (int kf = 0; kf < 4; kf++) {
                uint32_t pa0 = __float_as_uint(Ps[rr + g    ][kf * 8 + t4]);
                uint32_t pa1 = __float_as_uint(Ps[rr + g + 8][kf * 8 + t4]);
                uint32_t pa2 = __float_as_uint(Ps[rr + g    ][kf * 8 + t4 + 4]);
                uint32_t pa3 = __float_as_uint(Ps[rr + g + 8][kf * 8 + t4 + 4]);
                #pragma unroll
                for (int dn = 0; dn < 8; dn++) {
                    uint32_t b0 = __float_as_uint(Vs[sc][kf * 8 + t4    ][dn * 8 + g]);
                    uint32_t b1 = __float_as_uint(Vs[sc][kf * 8 + t4 + 4][dn * 8 + g]);
                    mma8(o[dn], pa0, pa1, pa2, pa3, b0, b1);
                }
            }
            __syncwarp();
        }

        if (++sc == 3) sc = 0;
    }

    const float inv0 = 1.0f / l0;
    const float inv1 = 1.0f / l1;
    const int r0 = q0 + warp * 16 + g;
    float* ob = g_attn + (size_t)b * SEQ * EMBED + (size_t)h * HEAD;
    #pragma unroll
    for (int dn = 0; dn < 8; dn++) {
        int d = dn * 8 + t4 * 2;
        ob[(size_t)(r0    ) * EMBED + d    ] = rnd32(o[dn][0] * inv0);
        ob[(size_t)(r0    ) * EMBED + d + 1] = rnd32(o[dn][1] * inv0);
        ob[(size_t)(r0 + 8) * EMBED + d    ] = rnd32(o[dn][2] * inv1);
        ob[(size_t)(r0 + 8) * EMBED + d + 1] = rnd32(o[dn][3] * inv1);
    }
}

// ============================================================================
// Kernel 3: output projection.  g_attn[8192,1024] @ g_wo^T + bo.
// ============================================================================
__global__ __launch_bounds__(128, 2) void proj_kernel(
    const float* __restrict__ bo,
    float* __restrict__ out)
{
    const int e0 = blockIdx.x * 128;
    const int m0 = blockIdx.y * 128;

    GemmAcc acc;
    #pragma unroll
    for (int mf = 0; mf < 4; mf++)
        #pragma unroll
        for (int ni = 0; ni < 8; ni++)
            #pragma unroll
            for (int e = 0; e < 4; e++) acc.c[mf][ni][e] = 0.0f;

    gemm128_body(acc, g_attn + (size_t)m0 * EMBED, g_wo + (size_t)e0 * EMBED,
                 EMBED, EMBED, EMBED / 16);

    const int lane = threadIdx.x & 31;
    const int warp = threadIdx.x >> 5;
    const int g    = lane >> 2;
    const int t4   = lane & 3;
    const int wm   = warp & 1;
    const int wn   = warp >> 1;

    #pragma unroll
    for (int mf = 0; mf < 4; mf++) {
        int r0 = m0 + wm * 64 + mf * 16 + g;
        #pragma unroll
        for (int ni = 0; ni < 8; ni++) {
            int e = e0 + wn * 64 + ni * 8 + t4 * 2;
            out[(size_t)(r0    ) * EMBED + e    ] = acc.c[mf][ni][0] + bo[e];
            out[(size_t)(r0    ) * EMBED + e + 1] = acc.c[mf][ni][1] + bo[e + 1];
            out[(size_t)(r0 + 8) * EMBED + e    ] = acc.c[mf][ni][2] + bo[e];
            out[(size_t)(r0 + 8) * EMBED + e + 1] = acc.c[mf][ni][3] + bo[e + 1];
        }
    }
}

// ============================================================================
extern "C" void kernel_launch(void* const* d_in, const int* in_sizes, int n_in,
                              void* d_out, int out_size)
{
    const float* x  = (const float*)d_in[0];
    const float* Wq = (const float*)d_in[1];
    const float* Wk = (const float*)d_in[2];
    const float* Wv = (const float*)d_in[3];
    const float* Wo = (const float*)d_in[4];
    const float* bo = (const float*)d_in[5];
    float* out = (float*)d_out;

    (void)in_sizes; (void)n_in; (void)out_size;

    cudaFuncSetAttribute(qkv_kernel,  cudaFuncAttributeMaxDynamicSharedMemorySize, GEMM_SMEM);
    cudaFuncSetAttribute(attn_kernel, cudaFuncAttributeMaxDynamicSharedMemorySize, ATTN_SMEM);
    cudaFuncSetAttribute(proj_kernel, cudaFuncAttributeMaxDynamicSharedMemorySize, GEMM_SMEM);

    round_x_kernel<<<NTOK * EMBED / 1024, 256>>>(x);
    pack_w_kernel<<<QKVN * EMBED / 256, 256>>>(Wq, Wk, Wv);
    round_wo_kernel<<<EMBED * EMBED / 1024, 256>>>(Wo);

    qkv_kernel<<<dim3(QKVN / 128, NTOK / 128), 128, GEMM_SMEM>>>();
    attn_kernel<<<dim3(SEQ / 128, BATCH * NHEADS), 256, ATTN_SMEM>>>();
    proj_kernel<<<dim3(EMBED / 128, NTOK / 128), 128, GEMM_SMEM>>>(bo, out);
}

// round 9
// speedup vs baseline: 1.2772x; 1.1944x over previous
#include <cuda_runtime.h>
#include <stdint.h>
#include <math.h>

#define BATCH  4
#define NHEADS 16
#define HEAD   64
#define SEQ    2048
#define EMBED  1024
#define QKVN   3072
#define NTOK   (BATCH * SEQ)   // 8192

// ---------------- scratch (device globals: allocation-free) ----------------
__device__ float g_q[BATCH * NHEADS * SEQ * HEAD];   // [B,H,S,D], tf32-rounded, Q pre-scaled
__device__ float g_k[BATCH * NHEADS * SEQ * HEAD];
__device__ float g_v[BATCH * NHEADS * SEQ * HEAD];
__device__ float g_attn[BATCH * SEQ * EMBED];        // [B,S,H*D], tf32-rounded
__device__ float g_xr[NTOK * EMBED];                 // X, tf32-rounded
__device__ float g_wqkv[EMBED * QKVN];               // packed [k][n], tf32-rounded
__device__ float g_wot[EMBED * EMBED];               // Wo^T [f][e], tf32-rounded

// ---------------- helpers ----------------
__device__ __forceinline__ float rnd32(float f) {
    uint32_t r;
    asm("cvt.rna.tf32.f32 %0, %1;" : "=r"(r) : "f"(f));
    return __uint_as_float(r);
}

__device__ __forceinline__ void mma8(float* c,
                                     uint32_t a0, uint32_t a1, uint32_t a2, uint32_t a3,
                                     uint32_t b0, uint32_t b1) {
    asm volatile(
        "mma.sync.aligned.m16n8k8.row.col.f32.tf32.tf32.f32 "
        "{%0,%1,%2,%3}, {%4,%5,%6,%7}, {%8,%9}, {%0,%1,%2,%3};"
        : "+f"(c[0]), "+f"(c[1]), "+f"(c[2]), "+f"(c[3])
        : "r"(a0), "r"(a1), "r"(a2), "r"(a3), "r"(b0), "r"(b1));
}

__device__ __forceinline__ void cp16(void* smem, const void* gmem) {
    uint32_t sa = (uint32_t)__cvta_generic_to_shared(smem);
    asm volatile("cp.async.cg.shared.global [%0], [%1], 16;" :: "r"(sa), "l"(gmem));
}
#define CP_COMMIT() asm volatile("cp.async.commit_group;")
#define CP_WAIT0()  asm volatile("cp.async.wait_group 0;")
#define CP_WAIT1()  asm volatile("cp.async.wait_group 1;")

// smem sizes (bytes)
#define GEMM_SMEM ((2 * 128 * 36 + 2 * 32 * 136) * 4)            // 71680
#define ATTN_SMEM ((3 * 32 * 68 + 3 * 32 * 72 + 128 * 36) * 4)   // 72192

// ============================================================================
// Prep kernels: round/pack operands once so inner loops need no cvt.
// ============================================================================
__global__ __launch_bounds__(256) void round_x_kernel(const float* __restrict__ x) {
    int i = (blockIdx.x * 256 + threadIdx.x) * 4;
    float4 v = *(const float4*)(x + i);
    v.x = rnd32(v.x); v.y = rnd32(v.y); v.z = rnd32(v.z); v.w = rnd32(v.w);
    *(float4*)(g_xr + i) = v;
}

// g_wqkv[k][n], n -> (mat, head, d)
__global__ __launch_bounds__(256) void pack_w_kernel(
    const float* __restrict__ Wq, const float* __restrict__ Wk, const float* __restrict__ Wv) {
    int i = blockIdx.x * 256 + threadIdx.x;      // over EMBED*QKVN
    int n = i % QKVN;
    int k = i / QKVN;
    int mat = n >> 10;
    int hn  = n & 1023;
    int h = hn >> 6, d = hn & 63;
    const float* w = (mat == 0) ? Wq : ((mat == 1) ? Wk : Wv);
    g_wqkv[i] = rnd32(w[((size_t)h * EMBED + k) * HEAD + d]);
}

__global__ __launch_bounds__(256) void trans_wo_kernel(const float* __restrict__ Wo) {
    __shared__ float t[32][33];
    const int e0 = blockIdx.x * 32;
    const int f0 = blockIdx.y * 32;
    const int tx = threadIdx.x & 31;
    const int ty = threadIdx.x >> 5;   // 0..7
    #pragma unroll
    for (int j = 0; j < 4; j++)
        t[ty + j * 8][tx] = Wo[(size_t)(e0 + ty + j * 8) * EMBED + f0 + tx];
    __syncthreads();
    #pragma unroll
    for (int j = 0; j < 4; j++)
        g_wot[(size_t)(f0 + ty + j * 8) * EMBED + e0 + tx] = rnd32(t[tx][ty + j * 8]);
}

// ============================================================================
// GEMM body: C[128x128] = A[128xK] * B[Kx128].  A rows strided lda,
// B k-major rows strided ldb.  K-chunk 32, 2-stage double buffer:
// 32 barriers total, 4x compute per barrier vs R5.
// 8 warps = 4(M) x 2(N); warp tile 32x64.
// ============================================================================
struct GemmAcc { float c[2][8][4]; };

__device__ __forceinline__ void gemm128_body(
    GemmAcc& acc,
    const float* __restrict__ aBase,   // A origin (row m0, col 0)
    const float* __restrict__ bBase,   // B origin (row 0, col n0)
    int lda, int ldb)
{
    extern __shared__ float smem[];
    float (*As)[128][36] = (float(*)[128][36])smem;                 // [st][m][k]
    float (*Bs)[32][136] = (float(*)[32][136])(smem + 2 * 128 * 36); // [st][k][n]

    const int tid  = threadIdx.x;
    const int lane = tid & 31;
    const int warp = tid >> 5;
    const int g    = lane >> 2;
    const int t4   = lane & 3;
    const int wm   = warp & 3;
    const int wn   = warp >> 2;

    // staging descriptors: A 128x32 = 1024 chunks, B 32x128 = 1024 chunks
    int ar[4], ac[4], bk[4], bn[4];
    const float* agp[4];
    const float* bgp[4];
    #pragma unroll
    for (int j = 0; j < 4; j++) {
        int chunk = tid + j * 256;
        ar[j] = chunk >> 3; ac[j] = (chunk & 7) * 4;
        agp[j] = aBase + (size_t)ar[j] * lda + ac[j];
        bk[j] = chunk >> 5; bn[j] = (chunk & 31) * 4;
        bgp[j] = bBase + (size_t)bk[j] * ldb + bn[j];
    }

    // prologue: chunk 0 into stage 0
    #pragma unroll
    for (int j = 0; j < 4; j++) {
        cp16(&As[0][ar[j]][ac[j]], agp[j]);
        cp16(&Bs[0][bk[j]][bn[j]], bgp[j]);
    }
    CP_COMMIT();
    CP_WAIT0();
    __syncthreads();

    const int NK = EMBED / 32;   // 32 chunks
    for (int it = 0; it < NK; it++) {
        const int buf = it & 1;
        if (it + 1 < NK) {
            const int kc = (it + 1) * 32;
            #pragma unroll
            for (int j = 0; j < 4; j++) {
                cp16(&As[buf ^ 1][ar[j]][ac[j]], agp[j] + kc);
                cp16(&Bs[buf ^ 1][bk[j]][bn[j]], bgp[j] + (size_t)kc * ldb);
            }
            CP_COMMIT();
        }

        #pragma unroll
        for (int ks = 0; ks < 4; ks++) {
            const int kb = ks * 8;
            uint32_t a[2][4];
            #pragma unroll
            for (int mi = 0; mi < 2; mi++) {
                int r = wm * 32 + mi * 16;
                a[mi][0] = __float_as_uint(As[buf][r + g    ][kb + t4]);
                a[mi][1] = __float_as_uint(As[buf][r + g + 8][kb + t4]);
                a[mi][2] = __float_as_uint(As[buf][r + g    ][kb + t4 + 4]);
                a[mi][3] = __float_as_uint(As[buf][r + g + 8][kb + t4 + 4]);
            }
            #pragma unroll
            for (int ni = 0; ni < 8; ni++) {
                uint32_t b0 = __float_as_uint(Bs[buf][kb + t4    ][wn * 64 + ni * 8 + g]);
                uint32_t b1 = __float_as_uint(Bs[buf][kb + t4 + 4][wn * 64 + ni * 8 + g]);
                #pragma unroll
                for (int mi = 0; mi < 2; mi++)
                    mma8(acc.c[mi][ni], a[mi][0], a[mi][1], a[mi][2], a[mi][3], b0, b1);
            }
        }

        if (it + 1 < NK) CP_WAIT0();
        __syncthreads();
    }
}

// ============================================================================
// Kernel 1: QKV GEMM -> scatter to g_q/g_k/g_v [B,H,S,D].
// ============================================================================
__global__ __launch_bounds__(256, 2) void qkv_kernel()
{
    const int n0 = blockIdx.x * 128;
    const int m0 = blockIdx.y * 128;

    GemmAcc acc;
    #pragma unroll
    for (int mi = 0; mi < 2; mi++)
        #pragma unroll
        for (int ni = 0; ni < 8; ni++)
            #pragma unroll
            for (int e = 0; e < 4; e++) acc.c[mi][ni][e] = 0.0f;

    gemm128_body(acc, g_xr + (size_t)m0 * EMBED, g_wqkv + n0, EMBED, QKVN);

    const int lane = threadIdx.x & 31;
    const int warp = threadIdx.x >> 5;
    const int g    = lane >> 2;
    const int t4   = lane & 3;
    const int wm   = warp & 3;
    const int wn   = warp >> 2;

    const int mat = n0 >> 10;
    const int b   = m0 >> 11;
    const int s0l = m0 & 2047;
    const int h   = ((n0 & 1023) >> 6) + wn;
    float* dstm = (mat == 0) ? g_q : ((mat == 1) ? g_k : g_v);
    float* dst  = dstm + ((size_t)(b * NHEADS + h) * SEQ) * HEAD;
    const float scale = (mat == 0) ? 0.125f : 1.0f;

    #pragma unroll
    for (int mi = 0; mi < 2; mi++) {
        int s0r = s0l + wm * 32 + mi * 16 + g;
        #pragma unroll
        for (int ni = 0; ni < 8; ni++) {
            int d = ni * 8 + t4 * 2;
            dst[(size_t)(s0r    ) * HEAD + d    ] = rnd32(acc.c[mi][ni][0] * scale);
            dst[(size_t)(s0r    ) * HEAD + d + 1] = rnd32(acc.c[mi][ni][1] * scale);
            dst[(size_t)(s0r + 8) * HEAD + d    ] = rnd32(acc.c[mi][ni][2] * scale);
            dst[(size_t)(s0r + 8) * HEAD + d + 1] = rnd32(acc.c[mi][ni][3] * scale);
        }
    }
}

// ============================================================================
// Kernel 2: causal flash attention (R5 core; occupancy 2).
// BM=128 (8 warps x 16 rows), BN=32, D=64, 3-stage cp.async K/V ring.
// ============================================================================
__global__ __launch_bounds__(256, 2) void attn_kernel()
{
    extern __shared__ float smem[];
    float (*Ks)[32][68] = (float(*)[32][68])smem;
    float (*Vs)[32][72] = (float(*)[32][72])(smem + 3 * 32 * 68);
    float (*Ps)[36]     = (float(*)[36])(smem + 3 * 32 * 68 + 3 * 32 * 72);

    const int bh = blockIdx.y;
    const int b  = bh >> 4;
    const int h  = bh & 15;
    const int qt = blockIdx.x;
    const int q0 = qt * 128;

    const int tid  = threadIdx.x;
    const int lane = tid & 31;
    const int warp = tid >> 5;
    const int g    = lane >> 2;
    const int t4   = lane & 3;

    const float* qp = g_q + ((size_t)bh * SEQ + q0) * HEAD;
    const float* kp = g_k + (size_t)bh * SEQ * HEAD;
    const float* vp = g_v + (size_t)bh * SEQ * HEAD;

    int cr[2], cd[2];
    #pragma unroll
    for (int j = 0; j < 2; j++) {
        int chunk = tid + j * 256;
        cr[j] = chunk >> 4; cd[j] = (chunk & 15) * 4;
    }

    uint32_t qa[8][4];
    #pragma unroll
    for (int round = 0; round < 2; round++) {
        const int c0 = round * 32;
        #pragma unroll
        for (int i = tid; i < 128 * 32; i += 256) {
            int r = i >> 5, cc = i & 31;
            Ps[r][cc] = qp[(size_t)r * HEAD + c0 + cc];
        }
        __syncthreads();
        #pragma unroll
        for (int kf = 0; kf < 4; kf++) {
            int kfi = round * 4 + kf;
            int rr = warp * 16;
            qa[kfi][0] = __float_as_uint(Ps[rr + g    ][kf * 8 + t4]);
            qa[kfi][1] = __float_as_uint(Ps[rr + g + 8][kf * 8 + t4]);
            qa[kfi][2] = __float_as_uint(Ps[rr + g    ][kf * 8 + t4 + 4]);
            qa[kfi][3] = __float_as_uint(Ps[rr + g + 8][kf * 8 + t4 + 4]);
        }
        __syncthreads();
    }

    float o[8][4];
    #pragma unroll
    for (int dn = 0; dn < 8; dn++)
        #pragma unroll
        for (int e = 0; e < 4; e++) o[dn][e] = 0.0f;

    float m0 = -1e30f, m1 = -1e30f, l0 = 0.0f, l1 = 0.0f;

    const int nkt   = (qt + 1) * 4;
    const int row0b = q0 + warp * 16;
    const int qmaxw = row0b + 15;

    #pragma unroll
    for (int st = 0; st < 2; st++) {
        const size_t base = (size_t)st * 32 * HEAD;
        #pragma unroll
        for (int j = 0; j < 2; j++) {
            cp16(&Ks[st][cr[j]][cd[j]], kp + base + (size_t)cr[j] * HEAD + cd[j]);
            cp16(&Vs[st][cr[j]][cd[j]], vp + base + (size_t)cr[j] * HEAD + cd[j]);
        }
        CP_COMMIT();
    }

    int sc = 0;
    for (int kt = 0; kt < nkt; kt++) {
        const int k0 = kt * 32;

        CP_WAIT1();
        __syncthreads();

        if (kt + 2 < nkt) {
            int sp = sc + 2; if (sp >= 3) sp -= 3;
            const size_t base = (size_t)(k0 + 64) * HEAD;
            #pragma unroll
            for (int j = 0; j < 2; j++) {
                cp16(&Ks[sp][cr[j]][cd[j]], kp + base + (size_t)cr[j] * HEAD + cd[j]);
                cp16(&Vs[sp][cr[j]][cd[j]], vp + base + (size_t)cr[j] * HEAD + cd[j]);
            }
            CP_COMMIT();
        }

        if (k0 <= qmaxw) {
            float s[4][4];
            #pragma unroll
            for (int nf = 0; nf < 4; nf++)
                #pragma unroll
                for (int e = 0; e < 4; e++) s[nf][e] = 0.0f;

            #pragma unroll
            for (int kf = 0; kf < 8; kf++) {
                #pragma unroll
                for (int nf = 0; nf < 4; nf++) {
                    uint32_t b0 = __float_as_uint(Ks[sc][nf * 8 + g][kf * 8 + t4]);
                    uint32_t b1 = __float_as_uint(Ks[sc][nf * 8 + g][kf * 8 + t4 + 4]);
                    mma8(s[nf], qa[kf][0], qa[kf][1], qa[kf][2], qa[kf][3], b0, b1);
                }
            }

            const int r0 = row0b + g;
            const int r1 = r0 + 8;
            #pragma unroll
            for (int nf = 0; nf < 4; nf++) {
                int col0 = k0 + nf * 8 + t4 * 2;
                if (col0     > r0) s[nf][0] = -1e30f;
                if (col0 + 1 > r0) s[nf][1] = -1e30f;
                if (col0     > r1) s[nf][2] = -1e30f;
                if (col0 + 1 > r1) s[nf][3] = -1e30f;
            }

            float rm0 = -1e30f, rm1 = -1e30f;
            #pragma unroll
            for (int nf = 0; nf < 4; nf++) {
                rm0 = fmaxf(rm0, fmaxf(s[nf][0], s[nf][1]));
                rm1 = fmaxf(rm1, fmaxf(s[nf][2], s[nf][3]));
            }
            rm0 = fmaxf(rm0, __shfl_xor_sync(0xffffffffu, rm0, 1));
            rm0 = fmaxf(rm0, __shfl_xor_sync(0xffffffffu, rm0, 2));
            rm1 = fmaxf(rm1, __shfl_xor_sync(0xffffffffu, rm1, 1));
            rm1 = fmaxf(rm1, __shfl_xor_sync(0xffffffffu, rm1, 2));

            float nm0 = fmaxf(m0, rm0), nm1 = fmaxf(m1, rm1);
            float sc0 = __expf(m0 - nm0), sc1 = __expf(m1 - nm1);

            float sum0 = 0.0f, sum1 = 0.0f;
            const int rr = warp * 16;
            #pragma unroll
            for (int nf = 0; nf < 4; nf++) {
                float p0 = rnd32(__expf(s[nf][0] - nm0));
                float p1 = rnd32(__expf(s[nf][1] - nm0));
                float p2 = rnd32(__expf(s[nf][2] - nm1));
                float p3 = rnd32(__expf(s[nf][3] - nm1));
                Ps[rr + g    ][nf * 8 + t4 * 2    ] = p0;
                Ps[rr + g    ][nf * 8 + t4 * 2 + 1] = p1;
                Ps[rr + g + 8][nf * 8 + t4 * 2    ] = p2;
                Ps[rr + g + 8][nf * 8 + t4 * 2 + 1] = p3;
                sum0 += p0 + p1;
                sum1 += p2 + p3;
            }
            sum0 += __shfl_xor_sync(0xffffffffu, sum0, 1);
            sum0 += __shfl_xor_sync(0xffffffffu, sum0, 2);
            sum1 += __shfl_xor_sync(0xffffffffu, sum1, 1);
            sum1 += __shfl_xor_sync(0xffffffffu, sum1, 2);

            l0 = l0 * sc0 + sum0;  m0 = nm0;
            l1 = l1 * sc1 + sum1;  m1 = nm1;

            #pragma unroll
            for (int dn = 0; dn < 8; dn++) {
                o[dn][0] *= sc0; o[dn][1] *= sc0;
                o[dn][2] *= sc1; o[dn][3] *= sc1;
            }
            __syncwarp();

            #pragma unroll
            for (int kf = 0; kf < 4; kf++) {
                uint32_t pa0 = __float_as_uint(Ps[rr + g    ][kf * 8 + t4]);
                uint32_t pa1 = __float_as_uint(Ps[rr + g + 8][kf * 8 + t4]);
                uint32_t pa2 = __float_as_uint(Ps[rr + g    ][kf * 8 + t4 + 4]);
                uint32_t pa3 = __float_as_uint(Ps[rr + g + 8][kf * 8 + t4 + 4]);
                #pragma unroll
                for (int dn = 0; dn < 8; dn++) {
                    uint32_t b0 = __float_as_uint(Vs[sc][kf * 8 + t4    ][dn * 8 + g]);
                    uint32_t b1 = __float_as_uint(Vs[sc][kf * 8 + t4 + 4][dn * 8 + g]);
                    mma8(o[dn], pa0, pa1, pa2, pa3, b0, b1);
                }
            }
            __syncwarp();
        }

        if (++sc == 3) sc = 0;
    }

    const float inv0 = 1.0f / l0;
    const float inv1 = 1.0f / l1;
    const int r0 = q0 + warp * 16 + g;
    float* ob = g_attn + (size_t)b * SEQ * EMBED + (size_t)h * HEAD;
    #pragma unroll
    for (int dn = 0; dn < 8; dn++) {
        int d = dn * 8 + t4 * 2;
        ob[(size_t)(r0    ) * EMBED + d    ] = rnd32(o[dn][0] * inv0);
        ob[(size_t)(r0    ) * EMBED + d + 1] = rnd32(o[dn][1] * inv0);
        ob[(size_t)(r0 + 8) * EMBED + d    ] = rnd32(o[dn][2] * inv1);
        ob[(size_t)(r0 + 8) * EMBED + d + 1] = rnd32(o[dn][3] * inv1);
    }
}

// ============================================================================
// Kernel 3: output projection.  g_attn[8192,1024] @ g_wot[1024,1024] + bo.
// ============================================================================
__global__ __launch_bounds__(256, 2) void proj_kernel(
    const float* __restrict__ bo,
    float* __restrict__ out)
{
    const int e0 = blockIdx.x * 128;
    const int m0 = blockIdx.y * 128;

    GemmAcc acc;
    #pragma unroll
    for (int mi = 0; mi < 2; mi++)
        #pragma unroll
        for (int ni = 0; ni < 8; ni++)
            #pragma unroll
            for (int e = 0; e < 4; e++) acc.c[mi][ni][e] = 0.0f;

    gemm128_body(acc, g_attn + (size_t)m0 * EMBED, g_wot + e0, EMBED, EMBED);

    const int lane = threadIdx.x & 31;
    const int warp = threadIdx.x >> 5;
    const int g    = lane >> 2;
    const int t4   = lane & 3;
    const int wm   = warp & 3;
    const int wn   = warp >> 2;

    #pragma unroll
    for (int mi = 0; mi < 2; mi++) {
        int r0 = m0 + wm * 32 + mi * 16 + g;
        #pragma unroll
        for (int ni = 0; ni < 8; ni++) {
            int e = e0 + wn * 64 + ni * 8 + t4 * 2;
            out[(size_t)(r0    ) * EMBED + e    ] = acc.c[mi][ni][0] + bo[e];
            out[(size_t)(r0    ) * EMBED + e + 1] = acc.c[mi][ni][1] + bo[e + 1];
            out[(size_t)(r0 + 8) * EMBED + e    ] = acc.c[mi][ni][2] + bo[e];
            out[(size_t)(r0 + 8) * EMBED + e + 1] = acc.c[mi][ni][3] + bo[e + 1];
        }
    }
}

// ============================================================================
extern "C" void kernel_launch(void* const* d_in, const int* in_sizes, int n_in,
                              void* d_out, int out_size)
{
    const float* x  = (const float*)d_in[0];
    const float* Wq = (const float*)d_in[1];
    const float* Wk = (const float*)d_in[2];
    const float* Wv = (const float*)d_in[3];
    const float* Wo = (const float*)d_in[4];
    const float* bo = (const float*)d_in[5];
    float* out = (float*)d_out;

    (void)in_sizes; (void)n_in; (void)out_size;

    cudaFuncSetAttribute(qkv_kernel,  cudaFuncAttributeMaxDynamicSharedMemorySize, GEMM_SMEM);
    cudaFuncSetAttribute(attn_kernel, cudaFuncAttributeMaxDynamicSharedMemorySize, ATTN_SMEM);
    cudaFuncSetAttribute(proj_kernel, cudaFuncAttributeMaxDynamicSharedMemorySize, GEMM_SMEM);

    round_x_kernel<<<NTOK * EMBED / 1024, 256>>>(x);
    pack_w_kernel<<<EMBED * QKVN / 256, 256>>>(Wq, Wk, Wv);
    trans_wo_kernel<<<dim3(EMBED / 32, EMBED / 32), 256>>>(Wo);

    qkv_kernel<<<dim3(QKVN / 128, NTOK / 128), 256, GEMM_SMEM>>>();
    attn_kernel<<<dim3(SEQ / 128, BATCH * NHEADS), 256, ATTN_SMEM>>>();
    proj_kernel<<<dim3(EMBED / 128, NTOK / 128), 256, GEMM_SMEM>>>(bo, out);
}